// round 13
// baseline (speedup 1.0000x reference)
#include <cuda_runtime.h>
#include <cuda_bf16.h>
#include <math.h>
#include <stdint.h>

#define LL 4096
#define CC 256
#define NBATCH 2
#define THRV 0.2f
#define MAXC 4096
#define NTILES 2048            // 2 * 32 * 32
#define QS 20.0f               // int8 quant scale
#define QINV (1.0f / (QS * QS * 16.0f))   // conf = dot_q * QINV  (incl. 1/sqrt(256))
#define ROWB 272               // padded int8 row bytes (256 + 16) -> conflict-free LDS
#define SCALEF 0.0625f         // 1/sqrt(256) for f32 rare-path dots

// ------------------------- device scratch (statically allocated) ------------
static __device__ int8_t g_q0[NBATCH * LL * CC];
static __device__ int8_t g_q1[NBATCH * LL * CC];
static __device__ float  g_rowPart[NBATCH * 32 * LL];
static __device__ float  g_colPart[NBATCH * 32 * LL];
static __device__ float  g_invR[NBATCH * LL];
static __device__ float  g_invC[NBATCH * LL];
static __device__ int    g_minR[NBATCH];
static __device__ int    g_minC[NBATCH];
static __device__ float  g_tileMax[NTILES];
static __device__ int    g_tileList[NTILES];
static __device__ int    g_tileCount;
static __device__ float  g_s0p[NBATCH * LL * 96];
static __device__ float  g_s1p[NBATCH * LL * 96];
static __device__ int    g_candCount;
static __device__ int    g_cand[MAXC];

__device__ __forceinline__ void cp16(void* smem, const void* gmem) {
    uint32_t s = (uint32_t)__cvta_generic_to_shared(smem);
    asm volatile("cp.async.cg.shared.global [%0], [%1], 16;\n" :: "r"(s), "l"(gmem));
}

// ------------------------- kernel 0: zero scratch ---------------------------
__global__ void k_zero() {
    int i = blockIdx.x * blockDim.x + threadIdx.x;
    const int tot = NBATCH * LL * 96;
    if (i < tot) { g_s0p[i] = 0.f; g_s1p[i] = 0.f; }
    if (i == 0) {
        g_candCount = 0; g_tileCount = 0;
        #pragma unroll
        for (int n = 0; n < NBATCH; n++) { g_minR[n] = 0x7F800000; g_minC[n] = 0x7F800000; }
    }
}

// ------------------------- kernel 1: f32 -> int8 (scale QS) -----------------
__global__ void k_convert(const float4* __restrict__ f0, const float4* __restrict__ f1) {
    int i = blockIdx.x * blockDim.x + threadIdx.x;
    if (i < NBATCH * LL * CC / 4) {
        float4 a = f0[i], b = f1[i];
        char4 qa, qb;
        qa.x = (char)__float2int_rn(fminf(fmaxf(a.x * QS, -127.f), 127.f));
        qa.y = (char)__float2int_rn(fminf(fmaxf(a.y * QS, -127.f), 127.f));
        qa.z = (char)__float2int_rn(fminf(fmaxf(a.z * QS, -127.f), 127.f));
        qa.w = (char)__float2int_rn(fminf(fmaxf(a.w * QS, -127.f), 127.f));
        qb.x = (char)__float2int_rn(fminf(fmaxf(b.x * QS, -127.f), 127.f));
        qb.y = (char)__float2int_rn(fminf(fmaxf(b.y * QS, -127.f), 127.f));
        qb.z = (char)__float2int_rn(fminf(fmaxf(b.z * QS, -127.f), 127.f));
        qb.w = (char)__float2int_rn(fminf(fmaxf(b.w * QS, -127.f), 127.f));
        ((char4*)g_q0)[i] = qa;
        ((char4*)g_q1)[i] = qb;
    }
}

// ------------------------- kernel 2: int8 GEMM, fused sums, no conf store ---
// conf[n][l][s] ~ dot_q(q0[n][l], q1[n][s]) * QINV  (never materialized).
// 128x128 tile, whole K=256 int8 resident (one-shot cp.async), 2 CTAs/SM,
// mma.sync.m16n8k32.s8 (2x math density vs bf16 k16 at same issue rate).
__global__ void __launch_bounds__(256, 2) k_gemm() {
    extern __shared__ int8_t sh[];        // A[128][272] + B[128][272] = 69,632 B
    int8_t* As = sh;
    int8_t* Bs = sh + 128 * ROWB;

    const int n  = blockIdx.z;
    const int bx = blockIdx.x;   // s tile
    const int by = blockIdx.y;   // l tile
    const int tid = threadIdx.x;

    const int8_t* gA = g_q0 + ((size_t)n * LL + (size_t)by * 128) * CC;
    const int8_t* gB = g_q1 + ((size_t)n * LL + (size_t)bx * 128) * CC;

    // one-shot load: 128 rows x 256 B per side, 16B chunks
    #pragma unroll
    for (int it = 0; it < 8; it++) {
        int ch = tid + it * 256;             // 0..2047
        int r = ch >> 4, c = (ch & 15) * 16;
        cp16(As + r * ROWB + c, gA + (size_t)r * CC + c);
        cp16(Bs + r * ROWB + c, gB + (size_t)r * CC + c);
    }
    asm volatile("cp.async.commit_group;\n" ::: "memory");
    asm volatile("cp.async.wait_group 0;\n" ::: "memory");
    __syncthreads();

    const int wid  = tid >> 5, lane = tid & 31;
    const int wm   = wid & 1,  wn   = wid >> 1;       // 2 (m) x 4 (n) warps
    const int m0   = wm * 64,  n0   = wn * 32;
    const int g    = lane >> 2, t   = lane & 3;

    int acc[4][4][4] = {};

    #pragma unroll
    for (int ks = 0; ks < 8; ks++) {
        const int kb = ks * 32;
        unsigned a[4][4], b[4][2];
        #pragma unroll
        for (int mt = 0; mt < 4; mt++) {
            const int8_t* base = As + (m0 + mt * 16 + g) * ROWB + kb + 4 * t;
            a[mt][0] = *(const unsigned*)(base);
            a[mt][1] = *(const unsigned*)(base + 8 * ROWB);
            a[mt][2] = *(const unsigned*)(base + 16);
            a[mt][3] = *(const unsigned*)(base + 8 * ROWB + 16);
        }
        #pragma unroll
        for (int nt = 0; nt < 4; nt++) {
            const int8_t* base = Bs + (n0 + nt * 8 + g) * ROWB + kb + 4 * t;
            b[nt][0] = *(const unsigned*)(base);
            b[nt][1] = *(const unsigned*)(base + 16);
        }
        #pragma unroll
        for (int mt = 0; mt < 4; mt++)
            #pragma unroll
            for (int nt = 0; nt < 4; nt++)
                asm volatile(
                    "mma.sync.aligned.m16n8k32.row.col.s32.s8.s8.s32 "
                    "{%0,%1,%2,%3}, {%4,%5,%6,%7}, {%8,%9}, {%0,%1,%2,%3};\n"
                    : "+r"(acc[mt][nt][0]), "+r"(acc[mt][nt][1]),
                      "+r"(acc[mt][nt][2]), "+r"(acc[mt][nt][3])
                    : "r"(a[mt][0]), "r"(a[mt][1]), "r"(a[mt][2]), "r"(a[mt][3]),
                      "r"(b[nt][0]), "r"(b[nt][1]));
    }
    __syncthreads();

    // ---- epilogue: stage exp(conf) f32 [128][133] + tile max + sums --------
    __shared__ float s_wm[8];
    float* sm = (float*)sh;    // 68,096 B <= 69,632 B (mainloop done)
    float mx = -1e30f;
    #pragma unroll
    for (int mt = 0; mt < 4; mt++) {
        #pragma unroll
        for (int nt = 0; nt < 4; nt++) {
            int r0 = m0 + mt * 16 + g;
            int c0 = n0 + nt * 8 + 2 * t;
            float v0 = (float)acc[mt][nt][0] * QINV, v1 = (float)acc[mt][nt][1] * QINV;
            float v2 = (float)acc[mt][nt][2] * QINV, v3 = (float)acc[mt][nt][3] * QINV;
            mx = fmaxf(mx, fmaxf(fmaxf(v0, v1), fmaxf(v2, v3)));
            sm[r0 * 133 + c0]           = __expf(v0);
            sm[r0 * 133 + c0 + 1]       = __expf(v1);
            sm[(r0 + 8) * 133 + c0]     = __expf(v2);
            sm[(r0 + 8) * 133 + c0 + 1] = __expf(v3);
        }
    }
    #pragma unroll
    for (int o = 16; o > 0; o >>= 1) mx = fmaxf(mx, __shfl_xor_sync(0xffffffffu, mx, o));
    if (lane == 0) s_wm[wid] = mx;
    __syncthreads();
    if (tid == 0) {
        float m = s_wm[0];
        #pragma unroll
        for (int w = 1; w < 8; w++) m = fmaxf(m, s_wm[w]);
        g_tileMax[n * 1024 + by * 32 + bx] = m;
    }

    // row / col partial sums of exp(conf)
    if (tid < 128) {
        float s = 0.f;
        #pragma unroll 4
        for (int c = 0; c < 128; c++) s += sm[tid * 133 + c];
        g_rowPart[((size_t)n * 32 + bx) * LL + by * 128 + tid] = s;
    } else {
        int c = tid - 128;
        float s = 0.f;
        #pragma unroll 4
        for (int r = 0; r < 128; r++) s += sm[r * 133 + c];
        g_colPart[((size_t)n * 32 + by) * LL + bx * 128 + c] = s;
    }
}

// ------------------------- kernel 3: reduce partials + mins -----------------
// grid 32, block 256: stage the 32x256 partial panel via coalesced loads.
__global__ void k_reduce() {
    __shared__ float sm[32 * 257];
    const int tid = threadIdx.x;
    const int o0 = blockIdx.x * 256;
    const int n = o0 >> 12;
    const int lbase = o0 & 4095;
    const int o = o0 + tid;

    #pragma unroll
    for (int it = 0; it < 32; it++)
        sm[it * 257 + tid] = g_rowPart[((size_t)n * 32 + it) * LL + lbase + tid];
    __syncthreads();
    float sr = 0.f;
    #pragma unroll
    for (int it = 0; it < 32; it++) sr += sm[it * 257 + tid];
    __syncthreads();

    #pragma unroll
    for (int it = 0; it < 32; it++)
        sm[it * 257 + tid] = g_colPart[((size_t)n * 32 + it) * LL + lbase + tid];
    __syncthreads();
    float sc = 0.f;
    #pragma unroll
    for (int it = 0; it < 32; it++) sc += sm[it * 257 + tid];

    g_invR[o] = 1.0f / sr;
    g_invC[o] = 1.0f / sc;

    int rb = __float_as_int(sr), cb = __float_as_int(sc);  // positive: int order
    #pragma unroll
    for (int off = 16; off > 0; off >>= 1) {
        rb = min(rb, __shfl_xor_sync(0xffffffffu, rb, off));
        cb = min(cb, __shfl_xor_sync(0xffffffffu, cb, off));
    }
    if ((tid & 31) == 0) { atomicMin(&g_minR[n], rb); atomicMin(&g_minC[n], cb); }
}

// ------------------------- kernel 4: tile screen ----------------------------
// p = e^{2c}/(R_l C_s) <= e^{2c}/(Rmin Cmin): tiles whose conf max is below
// 0.5*ln(THR*Rmin*Cmin) can contain no candidate.
__global__ void k_tilescan() {
    int i = blockIdx.x * blockDim.x + threadIdx.x;
    if (i >= NTILES) return;
    int n = i >> 10;
    float rm = __int_as_float(g_minR[n]);
    float cm = __int_as_float(g_minC[n]);
    float cthr = 0.5f * logf(THRV * rm * cm);
    if (g_tileMax[i] > cthr) {
        int idx = atomicAdd(&g_tileCount, 1);
        if (idx < NTILES) g_tileList[idx] = i;
    }
}

// ------------------------- kernel 5: rescan flagged tiles (rare) ------------
__global__ void k_rescan(const float* __restrict__ f0, const float* __restrict__ f1) {
    int count = g_tileCount; if (count > NTILES) count = NTILES;
    for (int ti = blockIdx.x; ti < count; ti += gridDim.x) {
        int tile = g_tileList[ti];
        int n = tile >> 10, by = (tile >> 5) & 31, bx = tile & 31;
        for (int el = threadIdx.x; el < 16384; el += blockDim.x) {
            int l = by * 128 + (el >> 7);
            int s = bx * 128 + (el & 127);
            const float4* a = (const float4*)(f0 + ((size_t)n * LL + l) * CC);
            const float4* b = (const float4*)(f1 + ((size_t)n * LL + s) * CC);
            float d = 0.f;
            #pragma unroll 8
            for (int k = 0; k < CC / 4; k++) {
                float4 av = a[k], bv = b[k];
                d += av.x * bv.x + av.y * bv.y + av.z * bv.z + av.w * bv.w;
            }
            float e = __expf(d * SCALEF);
            float p = e * e * g_invR[n * LL + l] * g_invC[n * LL + s];
            if (p > THRV) {
                int idx = atomicAdd(&g_candCount, 1);
                if (idx < MAXC) g_cand[idx] = (n << 24) | (l << 12) | s;
            }
        }
    }
}

// ------------------------- kernel 6: resolve rare matches -------------------
__device__ void accum_fea_pooled(const float* __restrict__ Xn, int loc,
                                 float* __restrict__ dst96) {
    __shared__ float sem[9];
    __shared__ float fea[CC];
    __shared__ float red2[CC];
    int c = threadIdx.x;
    int h = loc >> 6, w = loc & 63;
    float xlc = Xn[(size_t)loc * CC + c];
    float uv[9];
    #pragma unroll
    for (int w9 = 0; w9 < 9; w9++) {
        int dy = w9 / 3 - 1, dx = w9 % 3 - 1;
        int hh = h + dy, ww = w + dx;
        float u = 0.f;
        if (hh >= 0 && hh < 64 && ww >= 0 && ww < 64)
            u = Xn[(size_t)c * 4096 + hh * 64 + ww];   // raw (C,H,W) reinterpretation
        uv[w9] = u;
    }
    for (int w9 = 0; w9 < 9; w9++) {
        red2[c] = xlc * uv[w9];
        __syncthreads();
        for (int off = 128; off > 0; off >>= 1) {
            if (c < off) red2[c] += red2[c + off];
            __syncthreads();
        }
        if (c == 0) sem[w9] = red2[0] * (1.0f / CC);
        __syncthreads();
    }
    float f = 0.f;
    #pragma unroll
    for (int w9 = 0; w9 < 9; w9++) f += uv[w9] * sem[w9];
    fea[c] = f;
    __syncthreads();
    if (c < 96) {
        int st = (c * 256) / 96, en = ((c + 1) * 256 + 95) / 96;
        float s = 0.f;
        for (int q = st; q < en; q++) s += fea[q];
        atomicAdd(&dst96[c], (s / (float)(en - st)) * (1.0f / (float)LL));
    }
    __syncthreads();
}

__global__ void k_match(const float* __restrict__ f0, const float* __restrict__ f1) {
    __shared__ float a_row[CC];
    __shared__ float b_col[CC];
    __shared__ float red[256];
    int count = g_candCount; if (count > MAXC) count = MAXC;
    for (int ci = blockIdx.x; ci < count; ci += gridDim.x) {
        int id = g_cand[ci];
        int n = id >> 24, l = (id >> 12) & 4095, s = id & 4095;
        int t = threadIdx.x;
        a_row[t] = f0[((size_t)n * LL + l) * CC + t];
        b_col[t] = f1[((size_t)n * LL + s) * CC + t];
        __syncthreads();

        red[t] = a_row[t] * b_col[t]; __syncthreads();
        for (int off = 128; off > 0; off >>= 1) {
            if (t < off) red[t] += red[t + off];
            __syncthreads();
        }
        float e0 = __expf(red[0] * SCALEF);
        float p0 = e0 * e0 * g_invR[n * LL + l] * g_invC[n * LL + s];
        __syncthreads();

        float ir = g_invR[n * LL + l], ics = g_invC[n * LL + s];
        float m = -1e30f;
        for (int j = t; j < LL; j += 256) {
            const float* b = f1 + ((size_t)n * LL + j) * CC;
            float d = 0.f;
            #pragma unroll 8
            for (int k = 0; k < CC; k++) d += a_row[k] * b[k];
            float e = __expf(d * SCALEF);
            m = fmaxf(m, e * e * ir * g_invC[n * LL + j]);
        }
        red[t] = m; __syncthreads();
        for (int off = 128; off > 0; off >>= 1) {
            if (t < off) red[t] = fmaxf(red[t], red[t + off]);
            __syncthreads();
        }
        float rowmax = red[0]; __syncthreads();

        m = -1e30f;
        for (int j = t; j < LL; j += 256) {
            const float* a = f0 + ((size_t)n * LL + j) * CC;
            float d = 0.f;
            #pragma unroll 8
            for (int k = 0; k < CC; k++) d += a[k] * b_col[k];
            float e = __expf(d * SCALEF);
            m = fmaxf(m, e * e * g_invR[n * LL + j] * ics);
        }
        red[t] = m; __syncthreads();
        for (int off = 128; off > 0; off >>= 1) {
            if (t < off) red[t] = fmaxf(red[t], red[t + off]);
            __syncthreads();
        }
        float colmax = red[0]; __syncthreads();

        bool match = (p0 > THRV) && (p0 >= rowmax * (1.f - 1e-6f)) && (p0 >= colmax * (1.f - 1e-6f));
        if (match) {
            accum_fea_pooled(f1 + (size_t)n * LL * CC, s, g_s0p + ((size_t)n * LL + l) * 96);
            accum_fea_pooled(f0 + (size_t)n * LL * CC, l, g_s1p + ((size_t)n * LL + s) * 96);
        }
        __syncthreads();
    }
}

// ------------------------- kernel 7: pool + concat + LayerNorm --------------
__global__ void k_out(const float* __restrict__ f0, const float* __restrict__ f1,
                      const float* __restrict__ lw, const float* __restrict__ lb,
                      float* __restrict__ out) {
    __shared__ float frow[CC];
    int l = blockIdx.x, b = blockIdx.y;          // b in [0,4)
    int n = b & 1;
    const float* X  = (b < 2 ? f0 : f1) + ((size_t)n * LL + l) * CC;
    const float* sp = (b < 2 ? g_s0p : g_s1p) + ((size_t)n * LL + l) * 96;
    int t = threadIdx.x;
    frow[t] = X[t];
    __syncthreads();

    float val;
    if (t < 160) {
        int st = (t * 256) / 160, en = ((t + 1) * 256 + 159) / 160;
        float s = 0.f;
        for (int q = st; q < en; q++) s += frow[q];
        val = s / (float)(en - st);
    } else {
        val = sp[t - 160];
    }
    __syncthreads();

    frow[t] = val; __syncthreads();
    for (int off = 128; off > 0; off >>= 1) {
        if (t < off) frow[t] += frow[t + off];
        __syncthreads();
    }
    float mean = frow[0] * (1.0f / CC);
    __syncthreads();
    float d = val - mean;
    frow[t] = d * d; __syncthreads();
    for (int off = 128; off > 0; off >>= 1) {
        if (t < off) frow[t] += frow[t + off];
        __syncthreads();
    }
    float var = frow[0] * (1.0f / CC);
    float r = rsqrtf(var + 1e-5f);
    out[((size_t)b * LL + l) * CC + t] = d * r * lw[t] + lb[t];
}

// ------------------------- launch ------------------------------------------
extern "C" void kernel_launch(void* const* d_in, const int* in_sizes, int n_in,
                              void* d_out, int out_size) {
    const float* f0 = (const float*)d_in[0];
    const float* f1 = (const float*)d_in[1];
    const float* lw = (const float*)d_in[2];
    const float* lb = (const float*)d_in[3];
    float* out = (float*)d_out;
    (void)in_sizes; (void)n_in; (void)out_size;

    cudaFuncSetAttribute(k_gemm, cudaFuncAttributeMaxDynamicSharedMemorySize, 69632);

    k_zero<<<(NBATCH * LL * 96 + 511) / 512, 512>>>();
    k_convert<<<(NBATCH * LL * CC / 4 + 255) / 256, 256>>>((const float4*)f0, (const float4*)f1);
    k_gemm<<<dim3(32, 32, NBATCH), 256, 69632>>>();
    k_reduce<<<32, 256>>>();
    k_tilescan<<<(NTILES + 255) / 256, 256>>>();
    k_rescan<<<64, 256>>>(f0, f1);
    k_match<<<32, 256>>>(f0, f1);
    k_out<<<dim3(LL, 4), 256>>>(f0, f1, lw, lb, out);
}

// round 14
// speedup vs baseline: 1.8632x; 1.8632x over previous
#include <cuda_runtime.h>
#include <cuda_bf16.h>
#include <math.h>
#include <stdint.h>

#define LL 4096
#define CC 256
#define NBATCH 2
#define THRV 0.2f
#define MAXC 4096
#define NTILES 2048            // 2 * 32 * 32
#define SCALEF 0.0625f         // 1/sqrt(256)
#define APAD 72                // bf16 per smem row (64 + 8 pad)
#define STG_STRIDE (128 * APAD)

// ------------------------- device scratch (statically allocated) ------------
static __device__ __nv_bfloat16 g_bf0[NBATCH * LL * CC];
static __device__ __nv_bfloat16 g_bf1[NBATCH * LL * CC];
static __device__ float         g_rowPart[NBATCH * 32 * LL];
static __device__ float         g_colPart[NBATCH * 32 * LL];
static __device__ float         g_invR[NBATCH * LL];
static __device__ float         g_invC[NBATCH * LL];
static __device__ int           g_minR[NBATCH];
static __device__ int           g_minC[NBATCH];
static __device__ float         g_tileMax[NTILES];
static __device__ int           g_tileList[NTILES];
static __device__ int           g_tileCount;
static __device__ float         g_s0p[NBATCH * LL * 96];
static __device__ float         g_s1p[NBATCH * LL * 96];
static __device__ int           g_candCount;
static __device__ int           g_cand[MAXC];

__device__ __forceinline__ void cp16(__nv_bfloat16* smem, const __nv_bfloat16* gmem) {
    uint32_t s = (uint32_t)__cvta_generic_to_shared(smem);
    asm volatile("cp.async.cg.shared.global [%0], [%1], 16;\n" :: "r"(s), "l"(gmem));
}

// ------------------------- kernel 1: convert + zero (fused) -----------------
__global__ void k_convert(const float4* __restrict__ f0, const float4* __restrict__ f1) {
    int i = blockIdx.x * blockDim.x + threadIdx.x;
    const int nconv = NBATCH * LL * CC / 4;        // 524288
    if (i < nconv) {
        float4 a = f0[i], b = f1[i];
        __nv_bfloat162* o0 = (__nv_bfloat162*)g_bf0;
        __nv_bfloat162* o1 = (__nv_bfloat162*)g_bf1;
        o0[2 * i]     = __float22bfloat162_rn(make_float2(a.x, a.y));
        o0[2 * i + 1] = __float22bfloat162_rn(make_float2(a.z, a.w));
        o1[2 * i]     = __float22bfloat162_rn(make_float2(b.x, b.y));
        o1[2 * i + 1] = __float22bfloat162_rn(make_float2(b.z, b.w));
    }
    // zero masked-feature accumulators (786432 entries) + counters
    const int nz = NBATCH * LL * 96;
    if (i < nz) { g_s0p[i] = 0.f; g_s1p[i] = 0.f; }
    int i2 = i + nconv;
    if (i2 < nz) { g_s0p[i2] = 0.f; g_s1p[i2] = 0.f; }
    if (i == 0) {
        g_candCount = 0; g_tileCount = 0;
        #pragma unroll
        for (int n = 0; n < NBATCH; n++) { g_minR[n] = 0x7F800000; g_minC[n] = 0x7F800000; }
    }
}

// ------------------------- kernel 2: GEMM, fused sums, NO conf store --------
// conf[n][l][s] = dot(feat0[n][l], feat1[n][s]) / 16 (never materialized).
// 128x128 block tile, BK=64, 2-stage cp.async double buffer, 2 CTAs/SM.
// Epilogue: register-space exp + row/col sums via shuffles (no f32 staging).
__global__ void __launch_bounds__(256, 2) k_gemm() {
    extern __shared__ __nv_bfloat16 sh[];   // 2xA(128x72) + 2xB(128x72) = 72 KB

    const int n  = blockIdx.z;
    const int bx = blockIdx.x;   // s tile
    const int by = blockIdx.y;   // l tile
    const int tid = threadIdx.x;

    const __nv_bfloat16* gA0 = g_bf0 + ((size_t)n * LL + (size_t)by * 128) * CC;
    const __nv_bfloat16* gB0 = g_bf1 + ((size_t)n * LL + (size_t)bx * 128) * CC;

    auto load_stage = [&](int kc, int buf) {
        __nv_bfloat16* As = sh + buf * STG_STRIDE;
        __nv_bfloat16* Bs = sh + 2 * STG_STRIDE + buf * STG_STRIDE;
        const __nv_bfloat16* gA = gA0 + kc * 64;
        const __nv_bfloat16* gB = gB0 + kc * 64;
        #pragma unroll
        for (int it = 0; it < 4; it++) {
            int ch = tid + it * 256;           // 0..1023
            int r = ch >> 3, c = (ch & 7) * 8; // 8x16B chunks per 64-col row
            cp16(As + r * APAD + c, gA + (size_t)r * CC + c);
            cp16(Bs + r * APAD + c, gB + (size_t)r * CC + c);
        }
        asm volatile("cp.async.commit_group;\n" ::: "memory");
    };

    const int wid  = tid >> 5, lane = tid & 31;
    const int wm   = wid & 1,  wn   = wid >> 1;       // 2 (m) x 4 (n) warps
    const int m0   = wm * 64,  n0   = wn * 32;
    const int g    = lane >> 2, t   = lane & 3;

    float acc[4][4][4] = {};

    load_stage(0, 0);

    #pragma unroll
    for (int kc = 0; kc < 4; kc++) {
        if (kc < 3) {
            load_stage(kc + 1, (kc + 1) & 1);
            asm volatile("cp.async.wait_group 1;\n" ::: "memory");
        } else {
            asm volatile("cp.async.wait_group 0;\n" ::: "memory");
        }
        __syncthreads();

        const __nv_bfloat16* As = sh + (kc & 1) * STG_STRIDE;
        const __nv_bfloat16* Bs = sh + 2 * STG_STRIDE + (kc & 1) * STG_STRIDE;

        #pragma unroll
        for (int ks = 0; ks < 4; ks++) {
            const int kb = ks * 16;
            unsigned a[4][4], b[4][2];
            #pragma unroll
            for (int mt = 0; mt < 4; mt++) {
                const __nv_bfloat16* base = As + (m0 + mt * 16 + g) * APAD + kb;
                a[mt][0] = *(const unsigned*)(base + 2 * t);
                a[mt][1] = *(const unsigned*)(base + 8 * APAD + 2 * t);
                a[mt][2] = *(const unsigned*)(base + 8 + 2 * t);
                a[mt][3] = *(const unsigned*)(base + 8 * APAD + 8 + 2 * t);
            }
            #pragma unroll
            for (int nt = 0; nt < 4; nt++) {
                const __nv_bfloat16* base = Bs + (n0 + nt * 8 + g) * APAD + kb;
                b[nt][0] = *(const unsigned*)(base + 2 * t);
                b[nt][1] = *(const unsigned*)(base + 8 + 2 * t);
            }
            #pragma unroll
            for (int mt = 0; mt < 4; mt++)
                #pragma unroll
                for (int nt = 0; nt < 4; nt++)
                    asm volatile(
                        "mma.sync.aligned.m16n8k16.row.col.f32.bf16.bf16.f32 "
                        "{%0,%1,%2,%3}, {%4,%5,%6,%7}, {%8,%9}, {%0,%1,%2,%3};\n"
                        : "+f"(acc[mt][nt][0]), "+f"(acc[mt][nt][1]),
                          "+f"(acc[mt][nt][2]), "+f"(acc[mt][nt][3])
                        : "r"(a[mt][0]), "r"(a[mt][1]), "r"(a[mt][2]), "r"(a[mt][3]),
                          "r"(b[nt][0]), "r"(b[nt][1]));
        }
        __syncthreads();
    }

    // ---- epilogue: register-space exp + sums + tile max ---------------------
    // fragment map: acc[.][.][0,1] -> row r0,   cols c0, c0+1
    //               acc[.][.][2,3] -> row r0+8, cols c0, c0+1
    __shared__ float s_wm[8];
    __shared__ float rbuf[128 * 4];   // [row][wn]
    __shared__ float cbuf[128 * 2];   // [col][wm]

    float rsum[4][2] = {};            // [mt][half]
    float csum[4][2] = {};            // [nt][j]
    float mx = -1e30f;
    #pragma unroll
    for (int mt = 0; mt < 4; mt++) {
        #pragma unroll
        for (int nt = 0; nt < 4; nt++) {
            float v0 = acc[mt][nt][0] * SCALEF, v1 = acc[mt][nt][1] * SCALEF;
            float v2 = acc[mt][nt][2] * SCALEF, v3 = acc[mt][nt][3] * SCALEF;
            mx = fmaxf(mx, fmaxf(fmaxf(v0, v1), fmaxf(v2, v3)));
            float e0 = __expf(v0), e1 = __expf(v1), e2 = __expf(v2), e3 = __expf(v3);
            rsum[mt][0] += e0 + e1;
            rsum[mt][1] += e2 + e3;
            csum[nt][0] += e0 + e2;
            csum[nt][1] += e1 + e3;
        }
    }
    // row sums: reduce across t (quad)
    #pragma unroll
    for (int mt = 0; mt < 4; mt++)
        #pragma unroll
        for (int h = 0; h < 2; h++) {
            rsum[mt][h] += __shfl_xor_sync(0xffffffffu, rsum[mt][h], 1);
            rsum[mt][h] += __shfl_xor_sync(0xffffffffu, rsum[mt][h], 2);
        }
    // col sums: reduce across g (octet)
    #pragma unroll
    for (int nt = 0; nt < 4; nt++)
        #pragma unroll
        for (int j = 0; j < 2; j++) {
            csum[nt][j] += __shfl_xor_sync(0xffffffffu, csum[nt][j], 4);
            csum[nt][j] += __shfl_xor_sync(0xffffffffu, csum[nt][j], 8);
            csum[nt][j] += __shfl_xor_sync(0xffffffffu, csum[nt][j], 16);
        }
    if (t == 0) {
        #pragma unroll
        for (int mt = 0; mt < 4; mt++)
            #pragma unroll
            for (int h = 0; h < 2; h++)
                rbuf[(m0 + mt * 16 + g + 8 * h) * 4 + wn] = rsum[mt][h];
    }
    if (g == 0) {
        #pragma unroll
        for (int nt = 0; nt < 4; nt++)
            #pragma unroll
            for (int j = 0; j < 2; j++)
                cbuf[(n0 + nt * 8 + 2 * t + j) * 2 + wm] = csum[nt][j];
    }
    #pragma unroll
    for (int o = 16; o > 0; o >>= 1) mx = fmaxf(mx, __shfl_xor_sync(0xffffffffu, mx, o));
    if (lane == 0) s_wm[wid] = mx;
    __syncthreads();

    if (tid == 0) {
        float m = s_wm[0];
        #pragma unroll
        for (int w = 1; w < 8; w++) m = fmaxf(m, s_wm[w]);
        g_tileMax[n * 1024 + by * 32 + bx] = m;
    }
    if (tid < 128) {
        float s = rbuf[tid * 4] + rbuf[tid * 4 + 1] + rbuf[tid * 4 + 2] + rbuf[tid * 4 + 3];
        g_rowPart[((size_t)n * 32 + bx) * LL + by * 128 + tid] = s;
    } else {
        int c = tid - 128;
        g_colPart[((size_t)n * 32 + by) * LL + bx * 128 + c] = cbuf[c * 2] + cbuf[c * 2 + 1];
    }
}

// ------------------------- kernel 3: reduce partials + mins -----------------
__global__ void k_reduce() {   // grid 128, block 256 -> 4 threads per output
    int o   = blockIdx.x * 64 + (threadIdx.x >> 2);
    int sub = threadIdx.x & 3;
    int n = o >> 12, l = o & 4095;
    float sr = 0.f, sc = 0.f;
    #pragma unroll
    for (int t = sub; t < 32; t += 4) {
        sr += g_rowPart[((size_t)n * 32 + t) * LL + l];
        sc += g_colPart[((size_t)n * 32 + t) * LL + l];
    }
    sr += __shfl_xor_sync(0xffffffffu, sr, 1);
    sr += __shfl_xor_sync(0xffffffffu, sr, 2);
    sc += __shfl_xor_sync(0xffffffffu, sc, 1);
    sc += __shfl_xor_sync(0xffffffffu, sc, 2);
    if (sub == 0) { g_invR[o] = 1.0f / sr; g_invC[o] = 1.0f / sc; }
    int rb = __float_as_int(sr), cb = __float_as_int(sc);
    #pragma unroll
    for (int off = 16; off > 0; off >>= 1) {
        rb = min(rb, __shfl_xor_sync(0xffffffffu, rb, off));
        cb = min(cb, __shfl_xor_sync(0xffffffffu, cb, off));
    }
    if ((threadIdx.x & 31) == 0) { atomicMin(&g_minR[n], rb); atomicMin(&g_minC[n], cb); }
}

// ------------------------- kernel 4: tile screen ----------------------------
// p = e^{2c}/(R_l C_s) <= e^{2c}/(Rmin Cmin): tiles whose conf max is below
// 0.5*ln(THR*Rmin*Cmin) can contain no candidate.
__global__ void k_tilescan() {
    int i = blockIdx.x * blockDim.x + threadIdx.x;
    if (i >= NTILES) return;
    int n = i >> 10;
    float rm = __int_as_float(g_minR[n]);
    float cm = __int_as_float(g_minC[n]);
    float cthr = 0.5f * logf(THRV * rm * cm);
    if (g_tileMax[i] > cthr) {
        int idx = atomicAdd(&g_tileCount, 1);
        if (idx < NTILES) g_tileList[idx] = i;
    }
}

// ------------------------- kernel 5: rescan flagged tiles (rare) ------------
__global__ void k_rescan(const float* __restrict__ f0, const float* __restrict__ f1) {
    int count = g_tileCount; if (count > NTILES) count = NTILES;
    for (int ti = blockIdx.x; ti < count; ti += gridDim.x) {
        int tile = g_tileList[ti];
        int n = tile >> 10, by = (tile >> 5) & 31, bx = tile & 31;
        for (int el = threadIdx.x; el < 16384; el += blockDim.x) {
            int l = by * 128 + (el >> 7);
            int s = bx * 128 + (el & 127);
            const float4* a = (const float4*)(f0 + ((size_t)n * LL + l) * CC);
            const float4* b = (const float4*)(f1 + ((size_t)n * LL + s) * CC);
            float d = 0.f;
            #pragma unroll 8
            for (int k = 0; k < CC / 4; k++) {
                float4 av = a[k], bv = b[k];
                d += av.x * bv.x + av.y * bv.y + av.z * bv.z + av.w * bv.w;
            }
            float e = __expf(d * SCALEF);
            float p = e * e * g_invR[n * LL + l] * g_invC[n * LL + s];
            if (p > THRV) {
                int idx = atomicAdd(&g_candCount, 1);
                if (idx < MAXC) g_cand[idx] = (n << 24) | (l << 12) | s;
            }
        }
    }
}

// ------------------------- kernel 6: resolve rare matches -------------------
__device__ void accum_fea_pooled(const float* __restrict__ Xn, int loc,
                                 float* __restrict__ dst96) {
    __shared__ float sem[9];
    __shared__ float fea[CC];
    __shared__ float red2[CC];
    int c = threadIdx.x;
    int h = loc >> 6, w = loc & 63;
    float xlc = Xn[(size_t)loc * CC + c];
    float uv[9];
    #pragma unroll
    for (int w9 = 0; w9 < 9; w9++) {
        int dy = w9 / 3 - 1, dx = w9 % 3 - 1;
        int hh = h + dy, ww = w + dx;
        float u = 0.f;
        if (hh >= 0 && hh < 64 && ww >= 0 && ww < 64)
            u = Xn[(size_t)c * 4096 + hh * 64 + ww];   // raw (C,H,W) reinterpretation
        uv[w9] = u;
    }
    for (int w9 = 0; w9 < 9; w9++) {
        red2[c] = xlc * uv[w9];
        __syncthreads();
        for (int off = 128; off > 0; off >>= 1) {
            if (c < off) red2[c] += red2[c + off];
            __syncthreads();
        }
        if (c == 0) sem[w9] = red2[0] * (1.0f / CC);
        __syncthreads();
    }
    float f = 0.f;
    #pragma unroll
    for (int w9 = 0; w9 < 9; w9++) f += uv[w9] * sem[w9];
    fea[c] = f;
    __syncthreads();
    if (c < 96) {
        int st = (c * 256) / 96, en = ((c + 1) * 256 + 95) / 96;
        float s = 0.f;
        for (int q = st; q < en; q++) s += fea[q];
        atomicAdd(&dst96[c], (s / (float)(en - st)) * (1.0f / (float)LL));
    }
    __syncthreads();
}

__global__ void k_match(const float* __restrict__ f0, const float* __restrict__ f1) {
    __shared__ float a_row[CC];
    __shared__ float b_col[CC];
    __shared__ float red[256];
    int count = g_candCount; if (count > MAXC) count = MAXC;
    for (int ci = blockIdx.x; ci < count; ci += gridDim.x) {
        int id = g_cand[ci];
        int n = id >> 24, l = (id >> 12) & 4095, s = id & 4095;
        int t = threadIdx.x;
        a_row[t] = f0[((size_t)n * LL + l) * CC + t];
        b_col[t] = f1[((size_t)n * LL + s) * CC + t];
        __syncthreads();

        red[t] = a_row[t] * b_col[t]; __syncthreads();
        for (int off = 128; off > 0; off >>= 1) {
            if (t < off) red[t] += red[t + off];
            __syncthreads();
        }
        float e0 = __expf(red[0] * SCALEF);
        float p0 = e0 * e0 * g_invR[n * LL + l] * g_invC[n * LL + s];
        __syncthreads();

        float ir = g_invR[n * LL + l], ics = g_invC[n * LL + s];
        float m = -1e30f;
        for (int j = t; j < LL; j += 256) {
            const float* b = f1 + ((size_t)n * LL + j) * CC;
            float d = 0.f;
            #pragma unroll 8
            for (int k = 0; k < CC; k++) d += a_row[k] * b[k];
            float e = __expf(d * SCALEF);
            m = fmaxf(m, e * e * ir * g_invC[n * LL + j]);
        }
        red[t] = m; __syncthreads();
        for (int off = 128; off > 0; off >>= 1) {
            if (t < off) red[t] = fmaxf(red[t], red[t + off]);
            __syncthreads();
        }
        float rowmax = red[0]; __syncthreads();

        m = -1e30f;
        for (int j = t; j < LL; j += 256) {
            const float* a = f0 + ((size_t)n * LL + j) * CC;
            float d = 0.f;
            #pragma unroll 8
            for (int k = 0; k < CC; k++) d += a[k] * b_col[k];
            float e = __expf(d * SCALEF);
            m = fmaxf(m, e * e * g_invR[n * LL + j] * ics);
        }
        red[t] = m; __syncthreads();
        for (int off = 128; off > 0; off >>= 1) {
            if (t < off) red[t] = fmaxf(red[t], red[t + off]);
            __syncthreads();
        }
        float colmax = red[0]; __syncthreads();

        bool match = (p0 > THRV) && (p0 >= rowmax * (1.f - 1e-6f)) && (p0 >= colmax * (1.f - 1e-6f));
        if (match) {
            accum_fea_pooled(f1 + (size_t)n * LL * CC, s, g_s0p + ((size_t)n * LL + l) * 96);
            accum_fea_pooled(f0 + (size_t)n * LL * CC, l, g_s1p + ((size_t)n * LL + s) * 96);
        }
        __syncthreads();
    }
}

// ------------------------- kernel 7: pool + concat + LayerNorm --------------
__global__ void k_out(const float* __restrict__ f0, const float* __restrict__ f1,
                      const float* __restrict__ lw, const float* __restrict__ lb,
                      float* __restrict__ out) {
    __shared__ float frow[CC];
    __shared__ float s1[8], s2[8];
    int l = blockIdx.x, b = blockIdx.y;          // b in [0,4)
    int n = b & 1;
    const float* X  = (b < 2 ? f0 : f1) + ((size_t)n * LL + l) * CC;
    const float* sp = (b < 2 ? g_s0p : g_s1p) + ((size_t)n * LL + l) * 96;
    int t = threadIdx.x;
    frow[t] = X[t];
    __syncthreads();

    float val;
    if (t < 160) {
        int st = (t * 256) / 160, en = ((t + 1) * 256 + 159) / 160;
        float s = 0.f;
        for (int q = st; q < en; q++) s += frow[q];
        val = s / (float)(en - st);
    } else {
        val = sp[t - 160];
    }

    // two-moment warp-shuffle reduction
    float sA = val, sB = val * val;
    #pragma unroll
    for (int o = 16; o > 0; o >>= 1) {
        sA += __shfl_xor_sync(0xffffffffu, sA, o);
        sB += __shfl_xor_sync(0xffffffffu, sB, o);
    }
    if ((t & 31) == 0) { s1[t >> 5] = sA; s2[t >> 5] = sB; }
    __syncthreads();
    float tA = 0.f, tB = 0.f;
    #pragma unroll
    for (int w = 0; w < 8; w++) { tA += s1[w]; tB += s2[w]; }
    float mean = tA * (1.0f / CC);
    float var  = tB * (1.0f / CC) - mean * mean;
    float r = rsqrtf(var + 1e-5f);
    out[((size_t)b * LL + l) * CC + t] = (val - mean) * r * lw[t] + lb[t];
}

// ------------------------- launch ------------------------------------------
extern "C" void kernel_launch(void* const* d_in, const int* in_sizes, int n_in,
                              void* d_out, int out_size) {
    const float* f0 = (const float*)d_in[0];
    const float* f1 = (const float*)d_in[1];
    const float* lw = (const float*)d_in[2];
    const float* lb = (const float*)d_in[3];
    float* out = (float*)d_out;
    (void)in_sizes; (void)n_in; (void)out_size;

    cudaFuncSetAttribute(k_gemm, cudaFuncAttributeMaxDynamicSharedMemorySize, 73728);

    k_convert<<<(NBATCH * LL * CC / 4 + 511) / 512, 512>>>((const float4*)f0, (const float4*)f1);
    k_gemm<<<dim3(32, 32, NBATCH), 256, 73728>>>();
    k_reduce<<<128, 256>>>();
    k_tilescan<<<(NTILES + 255) / 256, 256>>>();
    k_rescan<<<64, 256>>>(f0, f1);
    k_match<<<32, 256>>>(f0, f1);
    k_out<<<dim3(LL, 4), 256>>>(f0, f1, lw, lb, out);
}

// round 15
// speedup vs baseline: 1.8644x; 1.0007x over previous
#include <cuda_runtime.h>
#include <cuda_bf16.h>
#include <math.h>
#include <stdint.h>

#define LL 4096
#define CC 256
#define NBATCH 2
#define THRV 0.2f
#define MAXC 4096
#define NTILES 2048            // 2 * 32 * 32
#define SCALEF 0.0625f         // 1/sqrt(256)
#define APAD 72                // bf16 per smem row (64 + 8 pad)
#define STG_STRIDE (128 * APAD)

// ------------------------- device scratch (statically allocated) ------------
static __device__ __nv_bfloat16 g_bf0[NBATCH * LL * CC];
static __device__ __nv_bfloat16 g_bf1[NBATCH * LL * CC];
static __device__ float         g_sumR[NBATCH * LL];   // atomic exp-sum accumulators
static __device__ float         g_sumC[NBATCH * LL];
static __device__ float         g_invR[NBATCH * LL];
static __device__ float         g_invC[NBATCH * LL];
static __device__ int           g_minR[NBATCH];
static __device__ int           g_minC[NBATCH];
static __device__ float         g_tileMax[NTILES];
static __device__ float         g_s0p[NBATCH * LL * 96];
static __device__ float         g_s1p[NBATCH * LL * 96];
static __device__ int           g_candCount;
static __device__ int           g_cand[MAXC];

__device__ __forceinline__ void cp16(__nv_bfloat16* smem, const __nv_bfloat16* gmem) {
    uint32_t s = (uint32_t)__cvta_generic_to_shared(smem);
    asm volatile("cp.async.cg.shared.global [%0], [%1], 16;\n" :: "r"(s), "l"(gmem));
}
__device__ __forceinline__ void ldsm4(unsigned& r0, unsigned& r1, unsigned& r2, unsigned& r3,
                                      uint32_t addr) {
    asm volatile("ldmatrix.sync.aligned.m8n8.x4.shared.b16 {%0,%1,%2,%3}, [%4];"
                 : "=r"(r0), "=r"(r1), "=r"(r2), "=r"(r3) : "r"(addr));
}

// ------------------------- kernel 1: convert + zero (fused) -----------------
__global__ void k_convert(const float4* __restrict__ f0, const float4* __restrict__ f1) {
    int i = blockIdx.x * blockDim.x + threadIdx.x;
    const int nconv = NBATCH * LL * CC / 4;        // 524288
    if (i < nconv) {
        float4 a = f0[i], b = f1[i];
        __nv_bfloat162* o0 = (__nv_bfloat162*)g_bf0;
        __nv_bfloat162* o1 = (__nv_bfloat162*)g_bf1;
        o0[2 * i]     = __float22bfloat162_rn(make_float2(a.x, a.y));
        o0[2 * i + 1] = __float22bfloat162_rn(make_float2(a.z, a.w));
        o1[2 * i]     = __float22bfloat162_rn(make_float2(b.x, b.y));
        o1[2 * i + 1] = __float22bfloat162_rn(make_float2(b.z, b.w));
    }
    const int nz = NBATCH * LL * 96;               // 786432
    if (i < nz) { g_s0p[i] = 0.f; g_s1p[i] = 0.f; }
    int i2 = i + nconv;
    if (i2 < nz) { g_s0p[i2] = 0.f; g_s1p[i2] = 0.f; }
    if (i < NBATCH * LL) { g_sumR[i] = 0.f; g_sumC[i] = 0.f; }
    if (i == 0) {
        g_candCount = 0;
        #pragma unroll
        for (int n = 0; n < NBATCH; n++) { g_minR[n] = 0x7F800000; g_minC[n] = 0x7F800000; }
    }
}

// ------------------------- kernel 2: GEMM, fused sums, NO conf store --------
// conf[n][l][s] = dot(feat0[n][l], feat1[n][s]) / 16 (never materialized).
// 128x128 block tile, BK=64, 2-stage cp.async double buffer, 2 CTAs/SM.
// Fragment loads via ldmatrix.x4 (6 LDSM vs 24 LDS.32 per thread per ks).
// Epilogue: register-space exp + row/col sums -> atomicAdd into g_sumR/g_sumC.
__global__ void __launch_bounds__(256, 2) k_gemm() {
    extern __shared__ __nv_bfloat16 sh[];   // 2xA(128x72) + 2xB(128x72) = 72 KB

    const int n  = blockIdx.z;
    const int bx = blockIdx.x;   // s tile
    const int by = blockIdx.y;   // l tile
    const int tid = threadIdx.x;

    const __nv_bfloat16* gA0 = g_bf0 + ((size_t)n * LL + (size_t)by * 128) * CC;
    const __nv_bfloat16* gB0 = g_bf1 + ((size_t)n * LL + (size_t)bx * 128) * CC;

    auto load_stage = [&](int kc, int buf) {
        __nv_bfloat16* As = sh + buf * STG_STRIDE;
        __nv_bfloat16* Bs = sh + 2 * STG_STRIDE + buf * STG_STRIDE;
        const __nv_bfloat16* gA = gA0 + kc * 64;
        const __nv_bfloat16* gB = gB0 + kc * 64;
        #pragma unroll
        for (int it = 0; it < 4; it++) {
            int ch = tid + it * 256;           // 0..1023
            int r = ch >> 3, c = (ch & 7) * 8; // 8x16B chunks per 64-col row
            cp16(As + r * APAD + c, gA + (size_t)r * CC + c);
            cp16(Bs + r * APAD + c, gB + (size_t)r * CC + c);
        }
        asm volatile("cp.async.commit_group;\n" ::: "memory");
    };

    const int wid  = tid >> 5, lane = tid & 31;
    const int wm   = wid & 1,  wn   = wid >> 1;       // 2 (m) x 4 (n) warps
    const int m0   = wm * 64,  n0   = wn * 32;
    const int g    = lane >> 2, t   = lane & 3;

    // ldmatrix lane address components (bf16-element offsets)
    const int quad = lane >> 3, rr = lane & 7;
    const int aRow = (quad & 1) * 8 + rr, aKad = (quad >> 1) * 8;   // A: m-dim rows
    const int bRow = (quad >> 1) * 8 + rr, bKad = (quad & 1) * 8;   // B: n-dim rows
    const uint32_t shBase = (uint32_t)__cvta_generic_to_shared(sh);

    float acc[4][4][4] = {};

    load_stage(0, 0);

    #pragma unroll
    for (int kc = 0; kc < 4; kc++) {
        if (kc < 3) {
            load_stage(kc + 1, (kc + 1) & 1);
            asm volatile("cp.async.wait_group 1;\n" ::: "memory");
        } else {
            asm volatile("cp.async.wait_group 0;\n" ::: "memory");
        }
        __syncthreads();

        const uint32_t aBuf = shBase + ((kc & 1) * STG_STRIDE) * 2;
        const uint32_t bBuf = shBase + ((2 + (kc & 1)) * STG_STRIDE) * 2;
        const uint32_t aLane = aBuf + ((m0 + aRow) * APAD + aKad) * 2;
        const uint32_t bLane = bBuf + ((n0 + bRow) * APAD + bKad) * 2;

        #pragma unroll
        for (int ks = 0; ks < 4; ks++) {
            const int kb2 = ks * 32;           // kb*2 bytes (kb = ks*16 bf16)
            unsigned a[4][4], b[4][2];
            #pragma unroll
            for (int mt = 0; mt < 4; mt++)
                ldsm4(a[mt][0], a[mt][1], a[mt][2], a[mt][3],
                      aLane + mt * 16 * APAD * 2 + kb2);
            #pragma unroll
            for (int p = 0; p < 2; p++)
                ldsm4(b[2 * p][0], b[2 * p][1], b[2 * p + 1][0], b[2 * p + 1][1],
                      bLane + p * 16 * APAD * 2 + kb2);
            #pragma unroll
            for (int mt = 0; mt < 4; mt++)
                #pragma unroll
                for (int nt = 0; nt < 4; nt++)
                    asm volatile(
                        "mma.sync.aligned.m16n8k16.row.col.f32.bf16.bf16.f32 "
                        "{%0,%1,%2,%3}, {%4,%5,%6,%7}, {%8,%9}, {%0,%1,%2,%3};\n"
                        : "+f"(acc[mt][nt][0]), "+f"(acc[mt][nt][1]),
                          "+f"(acc[mt][nt][2]), "+f"(acc[mt][nt][3])
                        : "r"(a[mt][0]), "r"(a[mt][1]), "r"(a[mt][2]), "r"(a[mt][3]),
                          "r"(b[nt][0]), "r"(b[nt][1]));
        }
        __syncthreads();
    }

    // ---- epilogue: register-space exp + sums + tile max ---------------------
    // fragment map: acc[.][.][0,1] -> row r0,   cols c0, c0+1
    //               acc[.][.][2,3] -> row r0+8, cols c0, c0+1
    __shared__ float s_wm[8];
    __shared__ float rbuf[128 * 4];   // [row][wn]
    __shared__ float cbuf[128 * 2];   // [col][wm]

    float rsum[4][2] = {};            // [mt][half]
    float csum[4][2] = {};            // [nt][j]
    float mx = -1e30f;
    #pragma unroll
    for (int mt = 0; mt < 4; mt++) {
        #pragma unroll
        for (int nt = 0; nt < 4; nt++) {
            float v0 = acc[mt][nt][0] * SCALEF, v1 = acc[mt][nt][1] * SCALEF;
            float v2 = acc[mt][nt][2] * SCALEF, v3 = acc[mt][nt][3] * SCALEF;
            mx = fmaxf(mx, fmaxf(fmaxf(v0, v1), fmaxf(v2, v3)));
            float e0 = __expf(v0), e1 = __expf(v1), e2 = __expf(v2), e3 = __expf(v3);
            rsum[mt][0] += e0 + e1;
            rsum[mt][1] += e2 + e3;
            csum[nt][0] += e0 + e2;
            csum[nt][1] += e1 + e3;
        }
    }
    #pragma unroll
    for (int mt = 0; mt < 4; mt++)
        #pragma unroll
        for (int h = 0; h < 2; h++) {
            rsum[mt][h] += __shfl_xor_sync(0xffffffffu, rsum[mt][h], 1);
            rsum[mt][h] += __shfl_xor_sync(0xffffffffu, rsum[mt][h], 2);
        }
    #pragma unroll
    for (int nt = 0; nt < 4; nt++)
        #pragma unroll
        for (int j = 0; j < 2; j++) {
            csum[nt][j] += __shfl_xor_sync(0xffffffffu, csum[nt][j], 4);
            csum[nt][j] += __shfl_xor_sync(0xffffffffu, csum[nt][j], 8);
            csum[nt][j] += __shfl_xor_sync(0xffffffffu, csum[nt][j], 16);
        }
    if (t == 0) {
        #pragma unroll
        for (int mt = 0; mt < 4; mt++)
            #pragma unroll
            for (int h = 0; h < 2; h++)
                rbuf[(m0 + mt * 16 + g + 8 * h) * 4 + wn] = rsum[mt][h];
    }
    if (g == 0) {
        #pragma unroll
        for (int nt = 0; nt < 4; nt++)
            #pragma unroll
            for (int j = 0; j < 2; j++)
                cbuf[(n0 + nt * 8 + 2 * t + j) * 2 + wm] = csum[nt][j];
    }
    #pragma unroll
    for (int o = 16; o > 0; o >>= 1) mx = fmaxf(mx, __shfl_xor_sync(0xffffffffu, mx, o));
    if (lane == 0) s_wm[wid] = mx;
    __syncthreads();

    if (tid == 0) {
        float m = s_wm[0];
        #pragma unroll
        for (int w = 1; w < 8; w++) m = fmaxf(m, s_wm[w]);
        g_tileMax[n * 1024 + by * 32 + bx] = m;
    }
    if (tid < 128) {
        float s = rbuf[tid * 4] + rbuf[tid * 4 + 1] + rbuf[tid * 4 + 2] + rbuf[tid * 4 + 3];
        atomicAdd(&g_sumR[n * LL + by * 128 + tid], s);
    } else {
        int c = tid - 128;
        atomicAdd(&g_sumC[n * LL + bx * 128 + c], cbuf[c * 2] + cbuf[c * 2 + 1]);
    }
}

// ------------------------- kernel 3: inverses + mins ------------------------
__global__ void k_small() {   // 16 blocks x 512 = 8192 threads
    int i = blockIdx.x * blockDim.x + threadIdx.x;
    if (i >= NBATCH * LL) return;
    int n = i >> 12;
    float sr = g_sumR[i], sc = g_sumC[i];
    g_invR[i] = 1.0f / sr;
    g_invC[i] = 1.0f / sc;
    int rb = __float_as_int(sr), cb = __float_as_int(sc);  // positive: int order
    #pragma unroll
    for (int off = 16; off > 0; off >>= 1) {
        rb = min(rb, __shfl_xor_sync(0xffffffffu, rb, off));
        cb = min(cb, __shfl_xor_sync(0xffffffffu, cb, off));
    }
    if ((threadIdx.x & 31) == 0) { atomicMin(&g_minR[n], rb); atomicMin(&g_minC[n], cb); }
}

// ------------------------- kernel 4: fused tile screen + rescan -------------
// p = e^{2c}/(R_l C_s) <= e^{2c}/(Rmin Cmin): tiles with conf max below
// 0.5*ln(THR*Rmin*Cmin) can contain no candidate; others get rescanned.
__global__ void k_scan2(const float* __restrict__ f0, const float* __restrict__ f1) {
    for (int tile = blockIdx.x; tile < NTILES; tile += gridDim.x) {
        int n = tile >> 10;
        float cthr = 0.5f * logf(THRV * __int_as_float(g_minR[n]) * __int_as_float(g_minC[n]));
        if (g_tileMax[tile] <= cthr) continue;
        int by = (tile >> 5) & 31, bx = tile & 31;
        for (int el = threadIdx.x; el < 16384; el += blockDim.x) {
            int l = by * 128 + (el >> 7);
            int s = bx * 128 + (el & 127);
            const float4* a = (const float4*)(f0 + ((size_t)n * LL + l) * CC);
            const float4* b = (const float4*)(f1 + ((size_t)n * LL + s) * CC);
            float d = 0.f;
            #pragma unroll 8
            for (int k = 0; k < CC / 4; k++) {
                float4 av = a[k], bv = b[k];
                d += av.x * bv.x + av.y * bv.y + av.z * bv.z + av.w * bv.w;
            }
            float e = __expf(d * SCALEF);
            float p = e * e * g_invR[n * LL + l] * g_invC[n * LL + s];
            if (p > THRV) {
                int idx = atomicAdd(&g_candCount, 1);
                if (idx < MAXC) g_cand[idx] = (n << 24) | (l << 12) | s;
            }
        }
    }
}

// ------------------------- kernel 5: resolve rare matches -------------------
__device__ void accum_fea_pooled(const float* __restrict__ Xn, int loc,
                                 float* __restrict__ dst96) {
    __shared__ float sem[9];
    __shared__ float fea[CC];
    __shared__ float red2[CC];
    int c = threadIdx.x;
    int h = loc >> 6, w = loc & 63;
    float xlc = Xn[(size_t)loc * CC + c];
    float uv[9];
    #pragma unroll
    for (int w9 = 0; w9 < 9; w9++) {
        int dy = w9 / 3 - 1, dx = w9 % 3 - 1;
        int hh = h + dy, ww = w + dx;
        float u = 0.f;
        if (hh >= 0 && hh < 64 && ww >= 0 && ww < 64)
            u = Xn[(size_t)c * 4096 + hh * 64 + ww];   // raw (C,H,W) reinterpretation
        uv[w9] = u;
    }
    for (int w9 = 0; w9 < 9; w9++) {
        red2[c] = xlc * uv[w9];
        __syncthreads();
        for (int off = 128; off > 0; off >>= 1) {
            if (c < off) red2[c] += red2[c + off];
            __syncthreads();
        }
        if (c == 0) sem[w9] = red2[0] * (1.0f / CC);
        __syncthreads();
    }
    float f = 0.f;
    #pragma unroll
    for (int w9 = 0; w9 < 9; w9++) f += uv[w9] * sem[w9];
    fea[c] = f;
    __syncthreads();
    if (c < 96) {
        int st = (c * 256) / 96, en = ((c + 1) * 256 + 95) / 96;
        float s = 0.f;
        for (int q = st; q < en; q++) s += fea[q];
        atomicAdd(&dst96[c], (s / (float)(en - st)) * (1.0f / (float)LL));
    }
    __syncthreads();
}

__global__ void k_match(const float* __restrict__ f0, const float* __restrict__ f1) {
    __shared__ float a_row[CC];
    __shared__ float b_col[CC];
    __shared__ float red[256];
    int count = g_candCount; if (count > MAXC) count = MAXC;
    for (int ci = blockIdx.x; ci < count; ci += gridDim.x) {
        int id = g_cand[ci];
        int n = id >> 24, l = (id >> 12) & 4095, s = id & 4095;
        int t = threadIdx.x;
        a_row[t] = f0[((size_t)n * LL + l) * CC + t];
        b_col[t] = f1[((size_t)n * LL + s) * CC + t];
        __syncthreads();

        red[t] = a_row[t] * b_col[t]; __syncthreads();
        for (int off = 128; off > 0; off >>= 1) {
            if (t < off) red[t] += red[t + off];
            __syncthreads();
        }
        float e0 = __expf(red[0] * SCALEF);
        float p0 = e0 * e0 * g_invR[n * LL + l] * g_invC[n * LL + s];
        __syncthreads();

        float ir = g_invR[n * LL + l], ics = g_invC[n * LL + s];
        float m = -1e30f;
        for (int j = t; j < LL; j += 256) {
            const float* b = f1 + ((size_t)n * LL + j) * CC;
            float d = 0.f;
            #pragma unroll 8
            for (int k = 0; k < CC; k++) d += a_row[k] * b[k];
            float e = __expf(d * SCALEF);
            m = fmaxf(m, e * e * ir * g_invC[n * LL + j]);
        }
        red[t] = m; __syncthreads();
        for (int off = 128; off > 0; off >>= 1) {
            if (t < off) red[t] = fmaxf(red[t], red[t + off]);
            __syncthreads();
        }
        float rowmax = red[0]; __syncthreads();

        m = -1e30f;
        for (int j = t; j < LL; j += 256) {
            const float* a = f0 + ((size_t)n * LL + j) * CC;
            float d = 0.f;
            #pragma unroll 8
            for (int k = 0; k < CC; k++) d += a[k] * b_col[k];
            float e = __expf(d * SCALEF);
            m = fmaxf(m, e * e * g_invR[n * LL + j] * ics);
        }
        red[t] = m; __syncthreads();
        for (int off = 128; off > 0; off >>= 1) {
            if (t < off) red[t] = fmaxf(red[t], red[t + off]);
            __syncthreads();
        }
        float colmax = red[0]; __syncthreads();

        bool match = (p0 > THRV) && (p0 >= rowmax * (1.f - 1e-6f)) && (p0 >= colmax * (1.f - 1e-6f));
        if (match) {
            accum_fea_pooled(f1 + (size_t)n * LL * CC, s, g_s0p + ((size_t)n * LL + l) * 96);
            accum_fea_pooled(f0 + (size_t)n * LL * CC, l, g_s1p + ((size_t)n * LL + s) * 96);
        }
        __syncthreads();
    }
}

// ------------------------- kernel 6: pool + concat + LayerNorm --------------
__global__ void k_out(const float* __restrict__ f0, const float* __restrict__ f1,
                      const float* __restrict__ lw, const float* __restrict__ lb,
                      float* __restrict__ out) {
    __shared__ float frow[CC];
    __shared__ float s1[8], s2[8];
    int l = blockIdx.x, b = blockIdx.y;          // b in [0,4)
    int n = b & 1;
    const float* X  = (b < 2 ? f0 : f1) + ((size_t)n * LL + l) * CC;
    const float* sp = (b < 2 ? g_s0p : g_s1p) + ((size_t)n * LL + l) * 96;
    int t = threadIdx.x;
    frow[t] = X[t];
    __syncthreads();

    float val;
    if (t < 160) {
        int st = (t * 256) / 160, en = ((t + 1) * 256 + 159) / 160;
        float s = 0.f;
        for (int q = st; q < en; q++) s += frow[q];
        val = s / (float)(en - st);
    } else {
        val = sp[t - 160];
    }

    float sA = val, sB = val * val;
    #pragma unroll
    for (int o = 16; o > 0; o >>= 1) {
        sA += __shfl_xor_sync(0xffffffffu, sA, o);
        sB += __shfl_xor_sync(0xffffffffu, sB, o);
    }
    if ((t & 31) == 0) { s1[t >> 5] = sA; s2[t >> 5] = sB; }
    __syncthreads();
    float tA = 0.f, tB = 0.f;
    #pragma unroll
    for (int w = 0; w < 8; w++) { tA += s1[w]; tB += s2[w]; }
    float mean = tA * (1.0f / CC);
    float var  = tB * (1.0f / CC) - mean * mean;
    float r = rsqrtf(var + 1e-5f);
    out[((size_t)b * LL + l) * CC + t] = (val - mean) * r * lw[t] + lb[t];
}

// ------------------------- launch ------------------------------------------
extern "C" void kernel_launch(void* const* d_in, const int* in_sizes, int n_in,
                              void* d_out, int out_size) {
    const float* f0 = (const float*)d_in[0];
    const float* f1 = (const float*)d_in[1];
    const float* lw = (const float*)d_in[2];
    const float* lb = (const float*)d_in[3];
    float* out = (float*)d_out;
    (void)in_sizes; (void)n_in; (void)out_size;

    cudaFuncSetAttribute(k_gemm, cudaFuncAttributeMaxDynamicSharedMemorySize, 73728);

    k_convert<<<(NBATCH * LL * CC / 4 + 511) / 512, 512>>>((const float4*)f0, (const float4*)f1);
    k_gemm<<<dim3(32, 32, NBATCH), 256, 73728>>>();
    k_small<<<16, 512>>>();
    k_scan2<<<64, 256>>>(f0, f1);
    k_match<<<32, 256>>>(f0, f1);
    k_out<<<dim3(LL, 4), 256>>>(f0, f1, lw, lb, out);
}

// round 16
// speedup vs baseline: 2.0403x; 1.0943x over previous
#include <cuda_runtime.h>
#include <cuda_bf16.h>
#include <math.h>
#include <stdint.h>

#define LL 4096
#define CC 256
#define NBATCH 2
#define THRV 0.2f
#define MAXC 4096
#define NTILES 2048            // 2 * 32 * 32
#define SCALEF 0.0625f         // 1/sqrt(256)
#define APAD 72                // bf16 per smem row (64 + 8 pad)
#define STG_STRIDE (128 * APAD)

// ------------------------- device scratch (statically allocated) ------------
static __device__ __nv_bfloat16 g_bf0[NBATCH * LL * CC];
static __device__ __nv_bfloat16 g_bf1[NBATCH * LL * CC];
static __device__ float         g_sumR[NBATCH * LL];   // atomic exp-sum accumulators
static __device__ float         g_sumC[NBATCH * LL];
static __device__ float         g_invR[NBATCH * LL];
static __device__ float         g_invC[NBATCH * LL];
static __device__ int           g_minR[NBATCH];
static __device__ int           g_minC[NBATCH];
static __device__ float         g_tileMax[NTILES];
static __device__ float         g_s0p[NBATCH * LL * 96];
static __device__ float         g_s1p[NBATCH * LL * 96];
static __device__ int           g_candCount;
static __device__ int           g_cand[MAXC];

__device__ __forceinline__ void cp16(__nv_bfloat16* smem, const __nv_bfloat16* gmem) {
    uint32_t s = (uint32_t)__cvta_generic_to_shared(smem);
    asm volatile("cp.async.cg.shared.global [%0], [%1], 16;\n" :: "r"(s), "l"(gmem));
}
__device__ __forceinline__ void ldsm4(unsigned& r0, unsigned& r1, unsigned& r2, unsigned& r3,
                                      uint32_t addr) {
    asm volatile("ldmatrix.sync.aligned.m8n8.x4.shared.b16 {%0,%1,%2,%3}, [%4];"
                 : "=r"(r0), "=r"(r1), "=r"(r2), "=r"(r3) : "r"(addr));
}

// ------------------------- kernel 1: convert + zero (fused) -----------------
__global__ void k_convert(const float4* __restrict__ f0, const float4* __restrict__ f1) {
    int i = blockIdx.x * blockDim.x + threadIdx.x;
    const int nconv = NBATCH * LL * CC / 4;        // 524288
    if (i < nconv) {
        float4 a = f0[i], b = f1[i];
        __nv_bfloat162* o0 = (__nv_bfloat162*)g_bf0;
        __nv_bfloat162* o1 = (__nv_bfloat162*)g_bf1;
        o0[2 * i]     = __float22bfloat162_rn(make_float2(a.x, a.y));
        o0[2 * i + 1] = __float22bfloat162_rn(make_float2(a.z, a.w));
        o1[2 * i]     = __float22bfloat162_rn(make_float2(b.x, b.y));
        o1[2 * i + 1] = __float22bfloat162_rn(make_float2(b.z, b.w));
    }
    const int nz = NBATCH * LL * 96;               // 786432
    if (i < nz) { g_s0p[i] = 0.f; g_s1p[i] = 0.f; }
    int i2 = i + nconv;
    if (i2 < nz) { g_s0p[i2] = 0.f; g_s1p[i2] = 0.f; }
    if (i < NBATCH * LL) { g_sumR[i] = 0.f; g_sumC[i] = 0.f; }
    if (i == 0) {
        g_candCount = 0;
        #pragma unroll
        for (int n = 0; n < NBATCH; n++) { g_minR[n] = 0x7F800000; g_minC[n] = 0x7F800000; }
    }
}

// ------------------------- kernel 2: GEMM, fused sums, NO conf store --------
// conf[n][l][s] = dot(feat0[n][l], feat1[n][s]) / 16 (never materialized).
// 128x128 block tile, BK=64, 2-stage cp.async double buffer, 2 CTAs/SM.
// Fragment loads via ldmatrix.x4; epilogue: register-space exp + row/col sums
// -> atomicAdd into g_sumR/g_sumC; per-tile conf max -> g_tileMax.
__global__ void __launch_bounds__(256, 2) k_gemm() {
    extern __shared__ __nv_bfloat16 sh[];   // 2xA(128x72) + 2xB(128x72) = 72 KB

    const int n  = blockIdx.z;
    const int bx = blockIdx.x;   // s tile
    const int by = blockIdx.y;   // l tile
    const int tid = threadIdx.x;

    const __nv_bfloat16* gA0 = g_bf0 + ((size_t)n * LL + (size_t)by * 128) * CC;
    const __nv_bfloat16* gB0 = g_bf1 + ((size_t)n * LL + (size_t)bx * 128) * CC;

    auto load_stage = [&](int kc, int buf) {
        __nv_bfloat16* As = sh + buf * STG_STRIDE;
        __nv_bfloat16* Bs = sh + 2 * STG_STRIDE + buf * STG_STRIDE;
        const __nv_bfloat16* gA = gA0 + kc * 64;
        const __nv_bfloat16* gB = gB0 + kc * 64;
        #pragma unroll
        for (int it = 0; it < 4; it++) {
            int ch = tid + it * 256;           // 0..1023
            int r = ch >> 3, c = (ch & 7) * 8; // 8x16B chunks per 64-col row
            cp16(As + r * APAD + c, gA + (size_t)r * CC + c);
            cp16(Bs + r * APAD + c, gB + (size_t)r * CC + c);
        }
        asm volatile("cp.async.commit_group;\n" ::: "memory");
    };

    const int wid  = tid >> 5, lane = tid & 31;
    const int wm   = wid & 1,  wn   = wid >> 1;       // 2 (m) x 4 (n) warps
    const int m0   = wm * 64,  n0   = wn * 32;
    const int g    = lane >> 2, t   = lane & 3;

    // ldmatrix lane address components (bf16-element offsets)
    const int quad = lane >> 3, rr = lane & 7;
    const int aRow = (quad & 1) * 8 + rr, aKad = (quad >> 1) * 8;   // A: m-dim rows
    const int bRow = (quad >> 1) * 8 + rr, bKad = (quad & 1) * 8;   // B: n-dim rows
    const uint32_t shBase = (uint32_t)__cvta_generic_to_shared(sh);

    float acc[4][4][4] = {};

    load_stage(0, 0);

    #pragma unroll
    for (int kc = 0; kc < 4; kc++) {
        if (kc < 3) {
            load_stage(kc + 1, (kc + 1) & 1);
            asm volatile("cp.async.wait_group 1;\n" ::: "memory");
        } else {
            asm volatile("cp.async.wait_group 0;\n" ::: "memory");
        }
        __syncthreads();

        const uint32_t aBuf = shBase + ((kc & 1) * STG_STRIDE) * 2;
        const uint32_t bBuf = shBase + ((2 + (kc & 1)) * STG_STRIDE) * 2;
        const uint32_t aLane = aBuf + ((m0 + aRow) * APAD + aKad) * 2;
        const uint32_t bLane = bBuf + ((n0 + bRow) * APAD + bKad) * 2;

        #pragma unroll
        for (int ks = 0; ks < 4; ks++) {
            const int kb2 = ks * 32;           // kb*2 bytes (kb = ks*16 bf16)
            unsigned a[4][4], b[4][2];
            #pragma unroll
            for (int mt = 0; mt < 4; mt++)
                ldsm4(a[mt][0], a[mt][1], a[mt][2], a[mt][3],
                      aLane + mt * 16 * APAD * 2 + kb2);
            #pragma unroll
            for (int p = 0; p < 2; p++)
                ldsm4(b[2 * p][0], b[2 * p][1], b[2 * p + 1][0], b[2 * p + 1][1],
                      bLane + p * 16 * APAD * 2 + kb2);
            #pragma unroll
            for (int mt = 0; mt < 4; mt++)
                #pragma unroll
                for (int nt = 0; nt < 4; nt++)
                    asm volatile(
                        "mma.sync.aligned.m16n8k16.row.col.f32.bf16.bf16.f32 "
                        "{%0,%1,%2,%3}, {%4,%5,%6,%7}, {%8,%9}, {%0,%1,%2,%3};\n"
                        : "+f"(acc[mt][nt][0]), "+f"(acc[mt][nt][1]),
                          "+f"(acc[mt][nt][2]), "+f"(acc[mt][nt][3])
                        : "r"(a[mt][0]), "r"(a[mt][1]), "r"(a[mt][2]), "r"(a[mt][3]),
                          "r"(b[nt][0]), "r"(b[nt][1]));
        }
        __syncthreads();
    }

    // ---- epilogue: register-space exp + sums + tile max ---------------------
    __shared__ float s_wm[8];
    __shared__ float rbuf[128 * 4];   // [row][wn]
    __shared__ float cbuf[128 * 2];   // [col][wm]

    float rsum[4][2] = {};            // [mt][half]
    float csum[4][2] = {};            // [nt][j]
    float mx = -1e30f;
    #pragma unroll
    for (int mt = 0; mt < 4; mt++) {
        #pragma unroll
        for (int nt = 0; nt < 4; nt++) {
            float v0 = acc[mt][nt][0] * SCALEF, v1 = acc[mt][nt][1] * SCALEF;
            float v2 = acc[mt][nt][2] * SCALEF, v3 = acc[mt][nt][3] * SCALEF;
            mx = fmaxf(mx, fmaxf(fmaxf(v0, v1), fmaxf(v2, v3)));
            float e0 = __expf(v0), e1 = __expf(v1), e2 = __expf(v2), e3 = __expf(v3);
            rsum[mt][0] += e0 + e1;
            rsum[mt][1] += e2 + e3;
            csum[nt][0] += e0 + e2;
            csum[nt][1] += e1 + e3;
        }
    }
    #pragma unroll
    for (int mt = 0; mt < 4; mt++)
        #pragma unroll
        for (int h = 0; h < 2; h++) {
            rsum[mt][h] += __shfl_xor_sync(0xffffffffu, rsum[mt][h], 1);
            rsum[mt][h] += __shfl_xor_sync(0xffffffffu, rsum[mt][h], 2);
        }
    #pragma unroll
    for (int nt = 0; nt < 4; nt++)
        #pragma unroll
        for (int j = 0; j < 2; j++) {
            csum[nt][j] += __shfl_xor_sync(0xffffffffu, csum[nt][j], 4);
            csum[nt][j] += __shfl_xor_sync(0xffffffffu, csum[nt][j], 8);
            csum[nt][j] += __shfl_xor_sync(0xffffffffu, csum[nt][j], 16);
        }
    if (t == 0) {
        #pragma unroll
        for (int mt = 0; mt < 4; mt++)
            #pragma unroll
            for (int h = 0; h < 2; h++)
                rbuf[(m0 + mt * 16 + g + 8 * h) * 4 + wn] = rsum[mt][h];
    }
    if (g == 0) {
        #pragma unroll
        for (int nt = 0; nt < 4; nt++)
            #pragma unroll
            for (int j = 0; j < 2; j++)
                cbuf[(n0 + nt * 8 + 2 * t + j) * 2 + wm] = csum[nt][j];
    }
    #pragma unroll
    for (int o = 16; o > 0; o >>= 1) mx = fmaxf(mx, __shfl_xor_sync(0xffffffffu, mx, o));
    if (lane == 0) s_wm[wid] = mx;
    __syncthreads();

    if (tid == 0) {
        float m = s_wm[0];
        #pragma unroll
        for (int w = 1; w < 8; w++) m = fmaxf(m, s_wm[w]);
        g_tileMax[n * 1024 + by * 32 + bx] = m;
    }
    if (tid < 128) {
        float s = rbuf[tid * 4] + rbuf[tid * 4 + 1] + rbuf[tid * 4 + 2] + rbuf[tid * 4 + 3];
        atomicAdd(&g_sumR[n * LL + by * 128 + tid], s);
    } else {
        int c = tid - 128;
        atomicAdd(&g_sumC[n * LL + bx * 128 + c], cbuf[c * 2] + cbuf[c * 2 + 1]);
    }
}

// ------------------------- kernel 3: inverses + mins ------------------------
__global__ void k_small() {   // 16 blocks x 512 = 8192 threads
    int i = blockIdx.x * blockDim.x + threadIdx.x;
    if (i >= NBATCH * LL) return;
    int n = i >> 12;
    float sr = g_sumR[i], sc = g_sumC[i];
    g_invR[i] = 1.0f / sr;
    g_invC[i] = 1.0f / sc;
    int rb = __float_as_int(sr), cb = __float_as_int(sc);  // positive: int order
    #pragma unroll
    for (int off = 16; off > 0; off >>= 1) {
        rb = min(rb, __shfl_xor_sync(0xffffffffu, rb, off));
        cb = min(cb, __shfl_xor_sync(0xffffffffu, cb, off));
    }
    if ((threadIdx.x & 31) == 0) { atomicMin(&g_minR[n], rb); atomicMin(&g_minC[n], cb); }
}

// ------------------------- kernel 4: tile screen + rescan (1 block/tile) ----
// p = e^{2c}/(R_l C_s) <= e^{2c}/(Rmin Cmin): tiles with conf max below
// 0.5*ln(THR*Rmin*Cmin) can contain no candidate; all blocks screen in
// parallel (one dependent load each) and early-exit on the common path.
__global__ void k_scan2(const float* __restrict__ f0, const float* __restrict__ f1) {
    __shared__ int s_flag;
    const int tile = blockIdx.x;
    const int n = tile >> 10;
    if (threadIdx.x == 0) {
        float cthr = 0.5f * logf(THRV * __int_as_float(g_minR[n]) * __int_as_float(g_minC[n]));
        s_flag = (g_tileMax[tile] > cthr) ? 1 : 0;
    }
    __syncthreads();
    if (!s_flag) return;

    const int by = (tile >> 5) & 31, bx = tile & 31;
    for (int el = threadIdx.x; el < 16384; el += blockDim.x) {
        int l = by * 128 + (el >> 7);
        int s = bx * 128 + (el & 127);
        const float4* a = (const float4*)(f0 + ((size_t)n * LL + l) * CC);
        const float4* b = (const float4*)(f1 + ((size_t)n * LL + s) * CC);
        float d = 0.f;
        #pragma unroll 8
        for (int k = 0; k < CC / 4; k++) {
            float4 av = a[k], bv = b[k];
            d += av.x * bv.x + av.y * bv.y + av.z * bv.z + av.w * bv.w;
        }
        float e = __expf(d * SCALEF);
        float p = e * e * g_invR[n * LL + l] * g_invC[n * LL + s];
        if (p > THRV) {
            int idx = atomicAdd(&g_candCount, 1);
            if (idx < MAXC) g_cand[idx] = (n << 24) | (l << 12) | s;
        }
    }
}

// ------------------------- kernel 5: resolve rare matches -------------------
__device__ void accum_fea_pooled(const float* __restrict__ Xn, int loc,
                                 float* __restrict__ dst96) {
    __shared__ float sem[9];
    __shared__ float fea[CC];
    __shared__ float red2[CC];
    int c = threadIdx.x;
    int h = loc >> 6, w = loc & 63;
    float xlc = Xn[(size_t)loc * CC + c];
    float uv[9];
    #pragma unroll
    for (int w9 = 0; w9 < 9; w9++) {
        int dy = w9 / 3 - 1, dx = w9 % 3 - 1;
        int hh = h + dy, ww = w + dx;
        float u = 0.f;
        if (hh >= 0 && hh < 64 && ww >= 0 && ww < 64)
            u = Xn[(size_t)c * 4096 + hh * 64 + ww];   // raw (C,H,W) reinterpretation
        uv[w9] = u;
    }
    for (int w9 = 0; w9 < 9; w9++) {
        red2[c] = xlc * uv[w9];
        __syncthreads();
        for (int off = 128; off > 0; off >>= 1) {
            if (c < off) red2[c] += red2[c + off];
            __syncthreads();
        }
        if (c == 0) sem[w9] = red2[0] * (1.0f / CC);
        __syncthreads();
    }
    float f = 0.f;
    #pragma unroll
    for (int w9 = 0; w9 < 9; w9++) f += uv[w9] * sem[w9];
    fea[c] = f;
    __syncthreads();
    if (c < 96) {
        int st = (c * 256) / 96, en = ((c + 1) * 256 + 95) / 96;
        float s = 0.f;
        for (int q = st; q < en; q++) s += fea[q];
        atomicAdd(&dst96[c], (s / (float)(en - st)) * (1.0f / (float)LL));
    }
    __syncthreads();
}

__global__ void k_match(const float* __restrict__ f0, const float* __restrict__ f1) {
    __shared__ float a_row[CC];
    __shared__ float b_col[CC];
    __shared__ float red[256];
    int count = g_candCount; if (count > MAXC) count = MAXC;
    for (int ci = blockIdx.x; ci < count; ci += gridDim.x) {
        int id = g_cand[ci];
        int n = id >> 24, l = (id >> 12) & 4095, s = id & 4095;
        int t = threadIdx.x;
        a_row[t] = f0[((size_t)n * LL + l) * CC + t];
        b_col[t] = f1[((size_t)n * LL + s) * CC + t];
        __syncthreads();

        red[t] = a_row[t] * b_col[t]; __syncthreads();
        for (int off = 128; off > 0; off >>= 1) {
            if (t < off) red[t] += red[t + off];
            __syncthreads();
        }
        float e0 = __expf(red[0] * SCALEF);
        float p0 = e0 * e0 * g_invR[n * LL + l] * g_invC[n * LL + s];
        __syncthreads();

        float ir = g_invR[n * LL + l], ics = g_invC[n * LL + s];
        float m = -1e30f;
        for (int j = t; j < LL; j += 256) {
            const float* b = f1 + ((size_t)n * LL + j) * CC;
            float d = 0.f;
            #pragma unroll 8
            for (int k = 0; k < CC; k++) d += a_row[k] * b[k];
            float e = __expf(d * SCALEF);
            m = fmaxf(m, e * e * ir * g_invC[n * LL + j]);
        }
        red[t] = m; __syncthreads();
        for (int off = 128; off > 0; off >>= 1) {
            if (t < off) red[t] = fmaxf(red[t], red[t + off]);
            __syncthreads();
        }
        float rowmax = red[0]; __syncthreads();

        m = -1e30f;
        for (int j = t; j < LL; j += 256) {
            const float* a = f0 + ((size_t)n * LL + j) * CC;
            float d = 0.f;
            #pragma unroll 8
            for (int k = 0; k < CC; k++) d += a[k] * b_col[k];
            float e = __expf(d * SCALEF);
            m = fmaxf(m, e * e * g_invR[n * LL + j] * ics);
        }
        red[t] = m; __syncthreads();
        for (int off = 128; off > 0; off >>= 1) {
            if (t < off) red[t] = fmaxf(red[t], red[t + off]);
            __syncthreads();
        }
        float colmax = red[0]; __syncthreads();

        bool match = (p0 > THRV) && (p0 >= rowmax * (1.f - 1e-6f)) && (p0 >= colmax * (1.f - 1e-6f));
        if (match) {
            accum_fea_pooled(f1 + (size_t)n * LL * CC, s, g_s0p + ((size_t)n * LL + l) * 96);
            accum_fea_pooled(f0 + (size_t)n * LL * CC, l, g_s1p + ((size_t)n * LL + s) * 96);
        }
        __syncthreads();
    }
}

// ------------------------- kernel 6: pool + concat + LayerNorm --------------
__global__ void k_out(const float* __restrict__ f0, const float* __restrict__ f1,
                      const float* __restrict__ lw, const float* __restrict__ lb,
                      float* __restrict__ out) {
    __shared__ float frow[CC];
    __shared__ float s1[8], s2[8];
    int l = blockIdx.x, b = blockIdx.y;          // b in [0,4)
    int n = b & 1;
    const float* X  = (b < 2 ? f0 : f1) + ((size_t)n * LL + l) * CC;
    const float* sp = (b < 2 ? g_s0p : g_s1p) + ((size_t)n * LL + l) * 96;
    int t = threadIdx.x;
    frow[t] = X[t];
    __syncthreads();

    float val;
    if (t < 160) {
        int st = (t * 256) / 160, en = ((t + 1) * 256 + 159) / 160;
        float s = 0.f;
        for (int q = st; q < en; q++) s += frow[q];
        val = s / (float)(en - st);
    } else {
        val = sp[t - 160];
    }

    float sA = val, sB = val * val;
    #pragma unroll
    for (int o = 16; o > 0; o >>= 1) {
        sA += __shfl_xor_sync(0xffffffffu, sA, o);
        sB += __shfl_xor_sync(0xffffffffu, sB, o);
    }
    if ((t & 31) == 0) { s1[t >> 5] = sA; s2[t >> 5] = sB; }
    __syncthreads();
    float tA = 0.f, tB = 0.f;
    #pragma unroll
    for (int w = 0; w < 8; w++) { tA += s1[w]; tB += s2[w]; }
    float mean = tA * (1.0f / CC);
    float var  = tB * (1.0f / CC) - mean * mean;
    float r = rsqrtf(var + 1e-5f);
    out[((size_t)b * LL + l) * CC + t] = (val - mean) * r * lw[t] + lb[t];
}

// ------------------------- launch ------------------------------------------
extern "C" void kernel_launch(void* const* d_in, const int* in_sizes, int n_in,
                              void* d_out, int out_size) {
    const float* f0 = (const float*)d_in[0];
    const float* f1 = (const float*)d_in[1];
    const float* lw = (const float*)d_in[2];
    const float* lb = (const float*)d_in[3];
    float* out = (float*)d_out;
    (void)in_sizes; (void)n_in; (void)out_size;

    cudaFuncSetAttribute(k_gemm, cudaFuncAttributeMaxDynamicSharedMemorySize, 73728);

    k_convert<<<(NBATCH * LL * CC / 4 + 511) / 512, 512>>>((const float4*)f0, (const float4*)f1);
    k_gemm<<<dim3(32, 32, NBATCH), 256, 73728>>>();
    k_small<<<16, 512>>>();
    k_scan2<<<NTILES, 256>>>(f0, f1);
    k_match<<<32, 256>>>(f0, f1);
    k_out<<<dim3(LL, 4), 256>>>(f0, f1, lw, lb, out);
}